// round 1
// baseline (speedup 1.0000x reference)
#include <cuda_runtime.h>
#include <math.h>

// Problem constants (hardcoded per reference: B=8, H=W=128, C=192, heads=6, hd=32, WS=8, shift=4)
#define TOKENS   131072          // B * H * W
#define CDIM     192
#define NHEADS   6
#define HD       32
#define NWIN     2048            // B * 16 * 16
#define HIDDEN   768

// Scratch (allocation-free: __device__ globals)
__device__ float g_winln[TOKENS * CDIM];      // LN1 output in windowed order
__device__ float g_qkv  [TOKENS * 3 * CDIM];  // qkv in windowed order
__device__ float g_attno[TOKENS * CDIM];      // attention output (windowed order)
__device__ float g_x2   [TOKENS * CDIM];      // shortcut + proj (token order)
__device__ float g_h2   [TOKENS * CDIM];      // LN2 output
__device__ float g_mlp  [TOKENS * HIDDEN];    // gelu(h2 @ w1 + b1)

// windowed row t -> token index (handles the cyclic shift by 4 in both directions;
// forward gather and reverse scatter use the same map since roll(-4) gather == roll(+4) scatter)
__device__ __forceinline__ int win_to_tok(int t) {
    int w = t >> 6, n = t & 63;
    int b  = w >> 8;
    int wi = (w >> 4) & 15;
    int wj = w & 15;
    int r = n >> 3, c = n & 7;
    int row = (wi * 8 + r + 4) & 127;
    int col = (wj * 8 + c + 4) & 127;
    return (b << 14) + (row << 7) + col;
}

// -------------------- LayerNorm (one warp per row of 192) --------------------
template <bool GATHER>
__global__ void ln_kernel(const float* __restrict__ in, float* __restrict__ out,
                          const float* __restrict__ gamma, const float* __restrict__ beta) {
    int warp = (blockIdx.x * blockDim.x + threadIdx.x) >> 5;
    int lane = threadIdx.x & 31;
    if (warp >= TOKENS) return;
    int src = GATHER ? win_to_tok(warp) : warp;
    const float* row = in + (size_t)src * CDIM;

    float v[6];
    float mu = 0.f;
#pragma unroll
    for (int i = 0; i < 6; i++) { v[i] = row[lane + 32 * i]; mu += v[i]; }
#pragma unroll
    for (int o = 16; o; o >>= 1) mu += __shfl_xor_sync(0xffffffffu, mu, o);
    mu *= (1.f / 192.f);
    float var = 0.f;
#pragma unroll
    for (int i = 0; i < 6; i++) { float d = v[i] - mu; var += d * d; }
#pragma unroll
    for (int o = 16; o; o >>= 1) var += __shfl_xor_sync(0xffffffffu, var, o);
    var *= (1.f / 192.f);
    float rstd = rsqrtf(var + 1e-5f);

    float* orow = out + (size_t)warp * CDIM;
#pragma unroll
    for (int i = 0; i < 6; i++) {
        int c = lane + 32 * i;
        orow[c] = (v[i] - mu) * rstd * gamma[c] + beta[c];
    }
}

// -------------------- Tiled fp32 GEMM with fused epilogues --------------------
// C[M,N] = A[M,K] @ B[K,N] + bias, tiles 64x64x16, 256 threads, 4x4 per thread.
// EPI: 0 = bias; 1 = bias+GELU(erf); 2 = bias + scatter(win_to_tok) + residual R (N=192);
//      3 = bias + residual R (same layout).
__device__ __forceinline__ float gelu_exact(float x) {
    return 0.5f * x * (1.0f + erff(x * 0.70710678118654752440f));
}

template <int EPI>
__global__ void gemm_kernel(const float* __restrict__ A, const float* __restrict__ B,
                            const float* __restrict__ bias, float* __restrict__ C,
                            const float* __restrict__ R,
                            int M, int N, int K) {
    __shared__ float As[16][68];   // A tile transposed: As[k][m]
    __shared__ float Bs[16][68];   // B tile: Bs[k][n]

    const int m0 = blockIdx.y * 64;
    const int n0 = blockIdx.x * 64;
    const int tid = threadIdx.x;
    const int tr = tid >> 4;       // 0..15 -> row group (4 rows)
    const int tc = tid & 15;       // 0..15 -> col group (4 cols)

    const int la_r = tid >> 2;           // 0..63
    const int la_k = (tid & 3) << 2;     // 0,4,8,12
    const int lb_k = tid >> 4;           // 0..15
    const int lb_c = (tid & 15) << 2;    // 0..60

    float acc[4][4];
#pragma unroll
    for (int i = 0; i < 4; i++)
#pragma unroll
        for (int j = 0; j < 4; j++) acc[i][j] = 0.f;

    for (int k0 = 0; k0 < K; k0 += 16) {
        float4 a = *(const float4*)(A + (size_t)(m0 + la_r) * K + k0 + la_k);
        float4 b = *(const float4*)(B + (size_t)(k0 + lb_k) * N + n0 + lb_c);
        As[la_k + 0][la_r] = a.x;
        As[la_k + 1][la_r] = a.y;
        As[la_k + 2][la_r] = a.z;
        As[la_k + 3][la_r] = a.w;
        *(float4*)&Bs[lb_k][lb_c] = b;
        __syncthreads();
#pragma unroll
        for (int kk = 0; kk < 16; kk++) {
            float4 af = *(const float4*)&As[kk][tr * 4];
            float4 bf = *(const float4*)&Bs[kk][tc * 4];
            float ar[4] = {af.x, af.y, af.z, af.w};
            float br[4] = {bf.x, bf.y, bf.z, bf.w};
#pragma unroll
            for (int i = 0; i < 4; i++)
#pragma unroll
                for (int j = 0; j < 4; j++) acc[i][j] += ar[i] * br[j];
        }
        __syncthreads();
    }

    const int nc = n0 + tc * 4;
    float4 bi = *(const float4*)&bias[nc];

#pragma unroll
    for (int i = 0; i < 4; i++) {
        int m = m0 + tr * 4 + i;
        float4 r;
        r.x = acc[i][0] + bi.x;
        r.y = acc[i][1] + bi.y;
        r.z = acc[i][2] + bi.z;
        r.w = acc[i][3] + bi.w;
        if (EPI == 1) {
            r.x = gelu_exact(r.x); r.y = gelu_exact(r.y);
            r.z = gelu_exact(r.z); r.w = gelu_exact(r.w);
        }
        if (EPI == 2) {
            int dst = win_to_tok(m);
            float4 res = *(const float4*)&R[(size_t)dst * CDIM + nc];
            r.x += res.x; r.y += res.y; r.z += res.z; r.w += res.w;
            *(float4*)&C[(size_t)dst * CDIM + nc] = r;
        } else if (EPI == 3) {
            float4 res = *(const float4*)&R[(size_t)m * N + nc];
            r.x += res.x; r.y += res.y; r.z += res.z; r.w += res.w;
            *(float4*)&C[(size_t)m * N + nc] = r;
        } else {
            *(float4*)&C[(size_t)m * N + nc] = r;
        }
    }
}

// -------------------- Windowed attention (one block per window x head) --------------------
__global__ void attn_kernel(const float* __restrict__ qkv, const float* __restrict__ rpb,
                            float* __restrict__ out) {
    const int bw = blockIdx.x;
    const int w = bw / NHEADS;
    const int h = bw - w * NHEADS;
    const int wi = (w >> 4) & 15;
    const int wj = w & 15;

    __shared__ float qs[64 * 33];
    __shared__ float ks[64 * 33];
    __shared__ float vs[64 * 33];
    __shared__ float ps[64 * 65];
    __shared__ float bshr[225];

    const int tid = threadIdx.x;
    const float scale = 0.1767766952966368811f; // 1/sqrt(32)

    const float* base = qkv + (size_t)w * 64 * (3 * CDIM) + h * HD;
#pragma unroll
    for (int i = 0; i < 8; i++) {
        int idx = tid + 256 * i;
        int n = idx >> 5, d = idx & 31;
        size_t r = (size_t)n * (3 * CDIM) + d;
        qs[n * 33 + d] = base[r] * scale;
        ks[n * 33 + d] = base[r + CDIM];
        vs[n * 33 + d] = base[r + 2 * CDIM];
    }
    if (tid < 225) bshr[tid] = rpb[tid * NHEADS + h];
    __syncthreads();

    const int n = tid >> 2;        // row 0..63 (4 lanes per row)
    const int mq = tid & 3;        // col quarter
    const int rn = n >> 3, cn = n & 7;
    const int lab_n = ((wi == 15) ? (rn < 4 ? 1 : 2) : 0) * 3 +
                      ((wj == 15) ? (cn < 4 ? 1 : 2) : 0);

    float qr[32];
#pragma unroll
    for (int d = 0; d < 32; d++) qr[d] = qs[n * 33 + d];

    float s[16];
#pragma unroll
    for (int mi = 0; mi < 16; mi++) {
        int m = mq * 16 + mi;
        float acc = 0.f;
#pragma unroll
        for (int d = 0; d < 32; d++) acc += qr[d] * ks[m * 33 + d];
        int rm = m >> 3, cm = m & 7;
        acc += bshr[(rn - rm + 7) * 15 + (cn - cm + 7)];
        int lab_m = ((wi == 15) ? (rm < 4 ? 1 : 2) : 0) * 3 +
                    ((wj == 15) ? (cm < 4 ? 1 : 2) : 0);
        if (lab_m != lab_n) acc -= 100.f;
        s[mi] = acc;
    }

    // softmax across the 4 lanes that share this row
    float mx = -1e30f;
#pragma unroll
    for (int mi = 0; mi < 16; mi++) mx = fmaxf(mx, s[mi]);
    mx = fmaxf(mx, __shfl_xor_sync(0xffffffffu, mx, 1));
    mx = fmaxf(mx, __shfl_xor_sync(0xffffffffu, mx, 2));
    float sum = 0.f;
#pragma unroll
    for (int mi = 0; mi < 16; mi++) { s[mi] = __expf(s[mi] - mx); sum += s[mi]; }
    sum += __shfl_xor_sync(0xffffffffu, sum, 1);
    sum += __shfl_xor_sync(0xffffffffu, sum, 2);
    float inv = 1.f / sum;
#pragma unroll
    for (int mi = 0; mi < 16; mi++) ps[n * 65 + mq * 16 + mi] = s[mi] * inv;
    __syncthreads();

    // out[n, d0..d0+7] = sum_m p[n][m] * v[m][d]
    const int d0 = (tid & 3) * 8;
    float o[8];
#pragma unroll
    for (int dd = 0; dd < 8; dd++) o[dd] = 0.f;
    for (int m = 0; m < 64; m++) {
        float p = ps[n * 65 + m];
#pragma unroll
        for (int dd = 0; dd < 8; dd++) o[dd] += p * vs[m * 33 + d0 + dd];
    }
    float* orow = out + ((size_t)w * 64 + n) * CDIM + h * HD + d0;
#pragma unroll
    for (int dd = 0; dd < 8; dd++) orow[dd] = o[dd];
}

// -------------------- launch --------------------
extern "C" void kernel_launch(void* const* d_in, const int* in_sizes, int n_in,
                              void* d_out, int out_size) {
    (void)in_sizes; (void)n_in; (void)out_size;
    const float* x      = (const float*)d_in[0];
    // d_in[1]=H, d_in[2]=W (hardcoded 128)
    const float* qkv_w  = (const float*)d_in[3];
    const float* qkv_b  = (const float*)d_in[4];
    const float* proj_w = (const float*)d_in[5];
    const float* proj_b = (const float*)d_in[6];
    const float* rpb    = (const float*)d_in[7];
    const float* n1w    = (const float*)d_in[8];
    const float* n1b    = (const float*)d_in[9];
    const float* n2w    = (const float*)d_in[10];
    const float* n2b    = (const float*)d_in[11];
    const float* w1     = (const float*)d_in[12];
    const float* b1     = (const float*)d_in[13];
    const float* w2     = (const float*)d_in[14];
    const float* b2     = (const float*)d_in[15];
    float* out = (float*)d_out;

    float *winln, *qkvb, *attno, *x2, *h2, *mlpg;
    cudaGetSymbolAddress((void**)&winln, g_winln);
    cudaGetSymbolAddress((void**)&qkvb,  g_qkv);
    cudaGetSymbolAddress((void**)&attno, g_attno);
    cudaGetSymbolAddress((void**)&x2,    g_x2);
    cudaGetSymbolAddress((void**)&h2,    g_h2);
    cudaGetSymbolAddress((void**)&mlpg,  g_mlp);

    // 1. LN1 + shift + window gather
    ln_kernel<true><<<TOKENS / 8, 256>>>(x, winln, n1w, n1b);
    // 2. QKV GEMM: [131072,192] @ [192,576]
    gemm_kernel<0><<<dim3(9, TOKENS / 64), 256>>>(winln, qkv_w, qkv_b, qkvb, nullptr,
                                                  TOKENS, 3 * CDIM, CDIM);
    // 3. Windowed attention
    attn_kernel<<<NWIN * NHEADS, 256>>>(qkvb, rpb, attno);
    // 4. Proj GEMM + window reverse/unshift scatter + shortcut residual -> x2
    gemm_kernel<2><<<dim3(3, TOKENS / 64), 256>>>(attno, proj_w, proj_b, x2, x,
                                                  TOKENS, CDIM, CDIM);
    // 5. LN2
    ln_kernel<false><<<TOKENS / 8, 256>>>(x2, h2, n2w, n2b);
    // 6. MLP1 + exact GELU: [131072,192] @ [192,768]
    gemm_kernel<1><<<dim3(12, TOKENS / 64), 256>>>(h2, w1, b1, mlpg, nullptr,
                                                   TOKENS, HIDDEN, CDIM);
    // 7. MLP2 + residual x2 -> out: [131072,768] @ [768,192]
    gemm_kernel<3><<<dim3(3, TOKENS / 64), 256>>>(mlpg, w2, b2, out, x2,
                                                  TOKENS, CDIM, HIDDEN);
}

// round 2
// speedup vs baseline: 1.6987x; 1.6987x over previous
#include <cuda_runtime.h>
#include <math.h>

// Problem constants (B=8, H=W=128, C=192, heads=6, hd=32, WS=8, shift=4)
#define TOKENS   131072
#define CDIM     192
#define NHEADS   6
#define HD       32
#define NWIN     2048
#define HIDDEN   768

__device__ float g_winln[TOKENS * CDIM];
__device__ float g_qkv  [TOKENS * 3 * CDIM];
__device__ float g_attno[TOKENS * CDIM];
__device__ float g_x2   [TOKENS * CDIM];
__device__ float g_h2   [TOKENS * CDIM];
__device__ float g_mlp  [TOKENS * HIDDEN];

__device__ __forceinline__ int win_to_tok(int t) {
    int w = t >> 6, n = t & 63;
    int b  = w >> 8;
    int wi = (w >> 4) & 15;
    int wj = w & 15;
    int r = n >> 3, c = n & 7;
    int row = (wi * 8 + r + 4) & 127;
    int col = (wj * 8 + c + 4) & 127;
    return (b << 14) + (row << 7) + col;
}

// -------------------- LayerNorm (one warp per row of 192) --------------------
template <bool GATHER>
__global__ void ln_kernel(const float* __restrict__ in, float* __restrict__ out,
                          const float* __restrict__ gamma, const float* __restrict__ beta) {
    int warp = (blockIdx.x * blockDim.x + threadIdx.x) >> 5;
    int lane = threadIdx.x & 31;
    if (warp >= TOKENS) return;
    int src = GATHER ? win_to_tok(warp) : warp;
    const float* row = in + (size_t)src * CDIM;

    float v[6];
    float mu = 0.f;
#pragma unroll
    for (int i = 0; i < 6; i++) { v[i] = row[lane + 32 * i]; mu += v[i]; }
#pragma unroll
    for (int o = 16; o; o >>= 1) mu += __shfl_xor_sync(0xffffffffu, mu, o);
    mu *= (1.f / 192.f);
    float var = 0.f;
#pragma unroll
    for (int i = 0; i < 6; i++) { float d = v[i] - mu; var += d * d; }
#pragma unroll
    for (int o = 16; o; o >>= 1) var += __shfl_xor_sync(0xffffffffu, var, o);
    var *= (1.f / 192.f);
    float rstd = rsqrtf(var + 1e-5f);

    float* orow = out + (size_t)warp * CDIM;
#pragma unroll
    for (int i = 0; i < 6; i++) {
        int c = lane + 32 * i;
        orow[c] = (v[i] - mu) * rstd * gamma[c] + beta[c];
    }
}

// -------------------- tf32 tensor-core GEMM with fused epilogues --------------------
__device__ __forceinline__ float gelu_exact(float x) {
    return 0.5f * x * (1.0f + erff(x * 0.70710678118654752440f));
}

__device__ __forceinline__ unsigned f2tf32(float x) {
    unsigned r;
    asm("cvt.rna.tf32.f32 %0, %1;" : "=r"(r) : "f"(x));
    return r;
}

__device__ __forceinline__ void mma_tf32(float* c, const unsigned* a, const unsigned* b) {
    asm volatile(
        "mma.sync.aligned.m16n8k8.row.col.f32.tf32.tf32.f32 "
        "{%0,%1,%2,%3},{%4,%5,%6,%7},{%8,%9},{%0,%1,%2,%3};"
        : "+f"(c[0]), "+f"(c[1]), "+f"(c[2]), "+f"(c[3])
        : "r"(a[0]), "r"(a[1]), "r"(a[2]), "r"(a[3]), "r"(b[0]), "r"(b[1]));
}

// Block tile 128(M) x 64(N) x 16(K); 256 threads = 8 warps (4 M x 2 N), warp tile 32x32.
// EPI: 0 = bias; 1 = bias+GELU; 2 = bias + scatter(win_to_tok) + residual (N=192);
//      3 = bias + residual.
#define AS_STRIDE 20
#define BS_STRIDE 72

template <int EPI>
__global__ void __launch_bounds__(256) gemm_tc(
        const float* __restrict__ A, const float* __restrict__ B,
        const float* __restrict__ bias, float* __restrict__ C,
        const float* __restrict__ R, int M, int N, int K) {
    __shared__ unsigned As[128 * AS_STRIDE];
    __shared__ unsigned Bs[16 * BS_STRIDE];

    const int m0 = blockIdx.y * 128;
    const int n0 = blockIdx.x * 64;
    const int tid = threadIdx.x;
    const int wid = tid >> 5;
    const int lane = tid & 31;
    const int mw = wid & 3;        // 0..3
    const int nw = wid >> 2;       // 0..1
    const int lr = lane >> 2;      // 0..7
    const int lc = lane & 3;       // 0..3

    // gmem load assignments
    const int arow = tid >> 1;            // 0..127
    const int acol = (tid & 1) * 8;       // 0 or 8
    const int brow = tid >> 4;            // 0..15
    const int bcol = (tid & 15) * 4;      // 0..60

    float acc[2][4][4];
#pragma unroll
    for (int i = 0; i < 2; i++)
#pragma unroll
        for (int j = 0; j < 4; j++)
#pragma unroll
            for (int l = 0; l < 4; l++) acc[i][j][l] = 0.f;

    const float* aptr = A + (size_t)(m0 + arow) * K + acol;
    const float* bptr = B + (size_t)brow * N + n0 + bcol;

    float4 pa0 = *(const float4*)(aptr);
    float4 pa1 = *(const float4*)(aptr + 4);
    float4 pb  = *(const float4*)(bptr);

    const int nsteps = K >> 4;
    for (int step = 0; step < nsteps; step++) {
        // stage current tile into smem (tf32-rounded)
        unsigned* as = &As[arow * AS_STRIDE + acol];
        as[0] = f2tf32(pa0.x); as[1] = f2tf32(pa0.y);
        as[2] = f2tf32(pa0.z); as[3] = f2tf32(pa0.w);
        as[4] = f2tf32(pa1.x); as[5] = f2tf32(pa1.y);
        as[6] = f2tf32(pa1.z); as[7] = f2tf32(pa1.w);
        unsigned* bs = &Bs[brow * BS_STRIDE + bcol];
        bs[0] = f2tf32(pb.x); bs[1] = f2tf32(pb.y);
        bs[2] = f2tf32(pb.z); bs[3] = f2tf32(pb.w);
        __syncthreads();

        // prefetch next tile
        if (step + 1 < nsteps) {
            const float* an = aptr + (step + 1) * 16;
            const float* bn = bptr + (size_t)(step + 1) * 16 * N;
            pa0 = *(const float4*)(an);
            pa1 = *(const float4*)(an + 4);
            pb  = *(const float4*)(bn);
        }

#pragma unroll
        for (int k8 = 0; k8 < 2; k8++) {
            unsigned af[2][4], bf[4][2];
#pragma unroll
            for (int mt = 0; mt < 2; mt++) {
                int base = (mw * 32 + mt * 16 + lr) * AS_STRIDE + k8 * 8 + lc;
                af[mt][0] = As[base];
                af[mt][1] = As[base + 8 * AS_STRIDE];
                af[mt][2] = As[base + 4];
                af[mt][3] = As[base + 8 * AS_STRIDE + 4];
            }
#pragma unroll
            for (int nt = 0; nt < 4; nt++) {
                int base = (k8 * 8 + lc) * BS_STRIDE + nw * 32 + nt * 8 + lr;
                bf[nt][0] = Bs[base];
                bf[nt][1] = Bs[base + 4 * BS_STRIDE];
            }
#pragma unroll
            for (int mt = 0; mt < 2; mt++)
#pragma unroll
                for (int nt = 0; nt < 4; nt++)
                    mma_tf32(acc[mt][nt], af[mt], bf[nt]);
        }
        __syncthreads();
    }

    // epilogue
#pragma unroll
    for (int mt = 0; mt < 2; mt++) {
#pragma unroll
        for (int nt = 0; nt < 4; nt++) {
            const float* c = acc[mt][nt];
            int col = n0 + nw * 32 + nt * 8 + 2 * lc;
            float bx = bias[col], by = bias[col + 1];
            int rbase = m0 + mw * 32 + mt * 16 + lr;
#pragma unroll
            for (int half = 0; half < 2; half++) {
                int m = rbase + half * 8;
                float vx = c[half * 2 + 0] + bx;
                float vy = c[half * 2 + 1] + by;
                if (EPI == 1) { vx = gelu_exact(vx); vy = gelu_exact(vy); }
                if (EPI == 2) {
                    int dst = win_to_tok(m);
                    size_t idx = (size_t)dst * CDIM + col;
                    float2 res = *(const float2*)&R[idx];
                    vx += res.x; vy += res.y;
                    *(float2*)&C[idx] = make_float2(vx, vy);
                } else if (EPI == 3) {
                    size_t idx = (size_t)m * N + col;
                    float2 res = *(const float2*)&R[idx];
                    vx += res.x; vy += res.y;
                    *(float2*)&C[idx] = make_float2(vx, vy);
                } else {
                    *(float2*)&C[(size_t)m * N + col] = make_float2(vx, vy);
                }
            }
        }
    }
}

// -------------------- Windowed attention (one block per window x head) --------------------
__global__ void attn_kernel(const float* __restrict__ qkv, const float* __restrict__ rpb,
                            float* __restrict__ out) {
    const int bw = blockIdx.x;
    const int w = bw / NHEADS;
    const int h = bw - w * NHEADS;
    const int wi = (w >> 4) & 15;
    const int wj = w & 15;

    __shared__ float qs[64 * 33];
    __shared__ float ks[64 * 33];
    __shared__ float vs[64 * 33];
    __shared__ float ps[64 * 65];
    __shared__ float bshr[225];

    const int tid = threadIdx.x;
    const float scale = 0.1767766952966368811f;

    const float* base = qkv + (size_t)w * 64 * (3 * CDIM) + h * HD;
#pragma unroll
    for (int i = 0; i < 8; i++) {
        int idx = tid + 256 * i;
        int n = idx >> 5, d = idx & 31;
        size_t r = (size_t)n * (3 * CDIM) + d;
        qs[n * 33 + d] = base[r] * scale;
        ks[n * 33 + d] = base[r + CDIM];
        vs[n * 33 + d] = base[r + 2 * CDIM];
    }
    if (tid < 225) bshr[tid] = rpb[tid * NHEADS + h];
    __syncthreads();

    const int n = tid >> 2;
    const int mq = tid & 3;
    const int rn = n >> 3, cn = n & 7;
    const int lab_n = ((wi == 15) ? (rn < 4 ? 1 : 2) : 0) * 3 +
                      ((wj == 15) ? (cn < 4 ? 1 : 2) : 0);

    float qr[32];
#pragma unroll
    for (int d = 0; d < 32; d++) qr[d] = qs[n * 33 + d];

    float s[16];
#pragma unroll
    for (int mi = 0; mi < 16; mi++) {
        int m = mq * 16 + mi;
        float acc = 0.f;
#pragma unroll
        for (int d = 0; d < 32; d++) acc += qr[d] * ks[m * 33 + d];
        int rm = m >> 3, cm = m & 7;
        acc += bshr[(rn - rm + 7) * 15 + (cn - cm + 7)];
        int lab_m = ((wi == 15) ? (rm < 4 ? 1 : 2) : 0) * 3 +
                    ((wj == 15) ? (cm < 4 ? 1 : 2) : 0);
        if (lab_m != lab_n) acc -= 100.f;
        s[mi] = acc;
    }

    float mx = -1e30f;
#pragma unroll
    for (int mi = 0; mi < 16; mi++) mx = fmaxf(mx, s[mi]);
    mx = fmaxf(mx, __shfl_xor_sync(0xffffffffu, mx, 1));
    mx = fmaxf(mx, __shfl_xor_sync(0xffffffffu, mx, 2));
    float sum = 0.f;
#pragma unroll
    for (int mi = 0; mi < 16; mi++) { s[mi] = __expf(s[mi] - mx); sum += s[mi]; }
    sum += __shfl_xor_sync(0xffffffffu, sum, 1);
    sum += __shfl_xor_sync(0xffffffffu, sum, 2);
    float inv = 1.f / sum;
#pragma unroll
    for (int mi = 0; mi < 16; mi++) ps[n * 65 + mq * 16 + mi] = s[mi] * inv;
    __syncthreads();

    const int d0 = (tid & 3) * 8;
    float o[8];
#pragma unroll
    for (int dd = 0; dd < 8; dd++) o[dd] = 0.f;
    for (int m = 0; m < 64; m++) {
        float p = ps[n * 65 + m];
#pragma unroll
        for (int dd = 0; dd < 8; dd++) o[dd] += p * vs[m * 33 + d0 + dd];
    }
    float* orow = out + ((size_t)w * 64 + n) * CDIM + h * HD + d0;
#pragma unroll
    for (int dd = 0; dd < 8; dd++) orow[dd] = o[dd];
}

// -------------------- launch --------------------
extern "C" void kernel_launch(void* const* d_in, const int* in_sizes, int n_in,
                              void* d_out, int out_size) {
    (void)in_sizes; (void)n_in; (void)out_size;
    const float* x      = (const float*)d_in[0];
    const float* qkv_w  = (const float*)d_in[3];
    const float* qkv_b  = (const float*)d_in[4];
    const float* proj_w = (const float*)d_in[5];
    const float* proj_b = (const float*)d_in[6];
    const float* rpb    = (const float*)d_in[7];
    const float* n1w    = (const float*)d_in[8];
    const float* n1b    = (const float*)d_in[9];
    const float* n2w    = (const float*)d_in[10];
    const float* n2b    = (const float*)d_in[11];
    const float* w1     = (const float*)d_in[12];
    const float* b1     = (const float*)d_in[13];
    const float* w2     = (const float*)d_in[14];
    const float* b2     = (const float*)d_in[15];
    float* out = (float*)d_out;

    float *winln, *qkvb, *attno, *x2, *h2, *mlpg;
    cudaGetSymbolAddress((void**)&winln, g_winln);
    cudaGetSymbolAddress((void**)&qkvb,  g_qkv);
    cudaGetSymbolAddress((void**)&attno, g_attno);
    cudaGetSymbolAddress((void**)&x2,    g_x2);
    cudaGetSymbolAddress((void**)&h2,    g_h2);
    cudaGetSymbolAddress((void**)&mlpg,  g_mlp);

    // 1. LN1 + shift + window gather
    ln_kernel<true><<<TOKENS / 8, 256>>>(x, winln, n1w, n1b);
    // 2. QKV GEMM: [131072,192] @ [192,576]
    gemm_tc<0><<<dim3(9, TOKENS / 128), 256>>>(winln, qkv_w, qkv_b, qkvb, nullptr,
                                               TOKENS, 3 * CDIM, CDIM);
    // 3. Windowed attention
    attn_kernel<<<NWIN * NHEADS, 256>>>(qkvb, rpb, attno);
    // 4. Proj GEMM + window reverse scatter + shortcut residual
    gemm_tc<2><<<dim3(3, TOKENS / 128), 256>>>(attno, proj_w, proj_b, x2, x,
                                               TOKENS, CDIM, CDIM);
    // 5. LN2
    ln_kernel<false><<<TOKENS / 8, 256>>>(x2, h2, n2w, n2b);
    // 6. MLP1 + exact GELU
    gemm_tc<1><<<dim3(12, TOKENS / 128), 256>>>(h2, w1, b1, mlpg, nullptr,
                                                TOKENS, HIDDEN, CDIM);
    // 7. MLP2 + residual
    gemm_tc<3><<<dim3(3, TOKENS / 128), 256>>>(mlpg, w2, b2, out, x2,
                                               TOKENS, CDIM, HIDDEN);
}

// round 3
// speedup vs baseline: 2.3890x; 1.4064x over previous
#include <cuda_runtime.h>
#include <cuda_bf16.h>
#include <math.h>

#define TOKENS   131072
#define CDIM     192
#define NHEADS   6
#define HD       32
#define NWIN     2048
#define HIDDEN   768

// ---- scratch (device globals; allocation-free) ----
__device__ __align__(16) __nv_bfloat16 g_winln[TOKENS * CDIM];
__device__ __align__(16) __nv_bfloat16 g_qkvb [TOKENS * 3 * CDIM];
__device__ __align__(16) __nv_bfloat16 g_attno[TOKENS * CDIM];
__device__ __align__(16) float         g_x2   [TOKENS * CDIM];
__device__ __align__(16) __nv_bfloat16 g_h2   [TOKENS * CDIM];
__device__ __align__(16) __nv_bfloat16 g_mlp  [TOKENS * HIDDEN];
// transposed bf16 weights: Wt[N][K]
__device__ __align__(16) __nv_bfloat16 g_qkvw_t[3 * CDIM * CDIM];
__device__ __align__(16) __nv_bfloat16 g_projw_t[CDIM * CDIM];
__device__ __align__(16) __nv_bfloat16 g_w1_t[HIDDEN * CDIM];
__device__ __align__(16) __nv_bfloat16 g_w2_t[CDIM * HIDDEN];

__device__ __forceinline__ int win_to_tok(int t) {
    int w = t >> 6, n = t & 63;
    int b  = w >> 8;
    int wi = (w >> 4) & 15;
    int wj = w & 15;
    int r = n >> 3, c = n & 7;
    int row = (wi * 8 + r + 4) & 127;
    int col = (wj * 8 + c + 4) & 127;
    return (b << 14) + (row << 7) + col;
}

// ---- weight convert + transpose: w[K][N] -> wt[N][K] bf16 ----
__global__ void wconv_kernel(const float* __restrict__ w, __nv_bfloat16* __restrict__ wt,
                             int K, int N) {
    int idx = blockIdx.x * 256 + threadIdx.x;
    if (idx >= K * N) return;
    int k = idx / N, n = idx - k * N;
    wt[n * K + k] = __float2bfloat16_rn(w[idx]);
}

// ---- LayerNorm: fp32 in -> bf16 out (one warp per row) ----
template <bool GATHER>
__global__ void ln_kernel(const float* __restrict__ in, __nv_bfloat16* __restrict__ out,
                          const float* __restrict__ gamma, const float* __restrict__ beta) {
    int warp = (blockIdx.x * blockDim.x + threadIdx.x) >> 5;
    int lane = threadIdx.x & 31;
    if (warp >= TOKENS) return;
    int src = GATHER ? win_to_tok(warp) : warp;
    const float* row = in + (size_t)src * CDIM;

    float v[6];
    float mu = 0.f;
#pragma unroll
    for (int i = 0; i < 6; i++) { v[i] = row[lane + 32 * i]; mu += v[i]; }
#pragma unroll
    for (int o = 16; o; o >>= 1) mu += __shfl_xor_sync(0xffffffffu, mu, o);
    mu *= (1.f / 192.f);
    float var = 0.f;
#pragma unroll
    for (int i = 0; i < 6; i++) { float d = v[i] - mu; var += d * d; }
#pragma unroll
    for (int o = 16; o; o >>= 1) var += __shfl_xor_sync(0xffffffffu, var, o);
    var *= (1.f / 192.f);
    float rstd = rsqrtf(var + 1e-5f);

    __nv_bfloat16* orow = out + (size_t)warp * CDIM;
#pragma unroll
    for (int i = 0; i < 6; i++) {
        int c = lane + 32 * i;
        orow[c] = __float2bfloat16_rn((v[i] - mu) * rstd * gamma[c] + beta[c]);
    }
}

// ---- bf16 tensor-core GEMM: C = A[M,K] @ Bt[N,K]^T + bias (+ epilogue) ----
__device__ __forceinline__ float gelu_exact(float x) {
    return 0.5f * x * (1.0f + erff(x * 0.70710678118654752440f));
}

__device__ __forceinline__ unsigned scvta(const void* p) {
    return (unsigned)__cvta_generic_to_shared(p);
}

__device__ __forceinline__ void ldsm4(unsigned* r, unsigned addr) {
    asm volatile("ldmatrix.sync.aligned.m8n8.x4.shared.b16 {%0,%1,%2,%3}, [%4];"
                 : "=r"(r[0]), "=r"(r[1]), "=r"(r[2]), "=r"(r[3]) : "r"(addr));
}

__device__ __forceinline__ void mma_bf16(float* c, const unsigned* a, const unsigned* b) {
    asm volatile("mma.sync.aligned.m16n8k16.row.col.f32.bf16.bf16.f32 "
                 "{%0,%1,%2,%3},{%4,%5,%6,%7},{%8,%9},{%0,%1,%2,%3};"
                 : "+f"(c[0]), "+f"(c[1]), "+f"(c[2]), "+f"(c[3])
                 : "r"(a[0]), "r"(a[1]), "r"(a[2]), "r"(a[3]), "r"(b[0]), "r"(b[1]));
}

// swizzled byte offset within a tile of 64B rows (4 chunks of 16B per row)
__device__ __forceinline__ int swz(int row, int chunk) {
    return row * 64 + ((chunk ^ ((row >> 1) & 3)) << 4);
}

// Block tile 128x64x32, 256 threads = 8 warps (4M x 2N), warp tile 32x32.
// EPI: 0 = bias (bf16 out); 1 = bias+GELU (bf16 out);
//      2 = bias + scatter + residual (fp32 out, N=192); 3 = bias + residual (fp32 out).
template <int EPI, typename OutT>
__global__ void __launch_bounds__(256) gemm_bf16(
        const __nv_bfloat16* __restrict__ A, const __nv_bfloat16* __restrict__ Bt,
        const float* __restrict__ bias, OutT* __restrict__ C,
        const float* __restrict__ R, int M, int N, int K) {
    __shared__ __align__(16) unsigned char smem[(128 + 64) * 64];
    unsigned char* As = smem;
    unsigned char* Bs = smem + 128 * 64;

    const int m0 = blockIdx.y * 128;
    const int n0 = blockIdx.x * 64;
    const int tid = threadIdx.x;
    const int lane = tid & 31;
    const int wid = tid >> 5;
    const int mw = wid & 3;
    const int nw = wid >> 2;

    // gmem->smem assignments
    const int a_row = tid >> 1;
    const int a_c0 = (tid & 1) * 2;
    const int b_row = tid >> 2;
    const int b_c = tid & 3;
    const __nv_bfloat16* aptr = A + (size_t)(m0 + a_row) * K + a_c0 * 8;
    const __nv_bfloat16* bptr = Bt + (size_t)(n0 + b_row) * K + b_c * 8;

    const int sA0 = swz(a_row, a_c0), sA1 = swz(a_row, a_c0 + 1), sB = swz(b_row, b_c);

    uint4 pa0 = *(const uint4*)aptr;
    uint4 pa1 = *(const uint4*)(aptr + 8);
    uint4 pb  = *(const uint4*)bptr;

    float acc[2][4][4];
#pragma unroll
    for (int i = 0; i < 2; i++)
#pragma unroll
        for (int j = 0; j < 4; j++)
#pragma unroll
            for (int l = 0; l < 4; l++) acc[i][j][l] = 0.f;

    // ldmatrix per-thread row assignments
    const int rowOffA = (lane & 7) + ((lane >> 3) & 1) * 8;  // matrix pairing for A
    const int cHalfA = lane >> 4;                            // k-half
    const int rowA0 = mw * 32 + rowOffA;
    const int rowOffB = ((lane >> 4) << 3) + (lane & 7);     // n-offset
    const int cHalfB = (lane >> 3) & 1;                      // k-half
    const int rowB0 = nw * 32 + rowOffB;

    const unsigned As_u = scvta(As);
    const unsigned Bs_u = scvta(Bs);

    const int nsteps = K >> 5;
    for (int step = 0; step < nsteps; step++) {
        *(uint4*)(As + sA0) = pa0;
        *(uint4*)(As + sA1) = pa1;
        *(uint4*)(Bs + sB) = pb;
        __syncthreads();
        if (step + 1 < nsteps) {
            pa0 = *(const uint4*)(aptr + (step + 1) * 32);
            pa1 = *(const uint4*)(aptr + (step + 1) * 32 + 8);
            pb  = *(const uint4*)(bptr + (step + 1) * 32);
        }
#pragma unroll
        for (int s = 0; s < 2; s++) {
            unsigned af[2][4], bf[2][4];
            const int chA = 2 * s + cHalfA;
            const int chB = 2 * s + cHalfB;
#pragma unroll
            for (int t = 0; t < 2; t++) {
                int row = rowA0 + t * 16;
                ldsm4(af[t], As_u + row * 64 + ((chA ^ ((row >> 1) & 3)) << 4));
            }
#pragma unroll
            for (int t = 0; t < 2; t++) {
                int row = rowB0 + t * 16;
                ldsm4(bf[t], Bs_u + row * 64 + ((chB ^ ((row >> 1) & 3)) << 4));
            }
#pragma unroll
            for (int mt = 0; mt < 2; mt++)
#pragma unroll
                for (int nt = 0; nt < 4; nt++)
                    mma_bf16(acc[mt][nt], af[mt], &bf[nt >> 1][(nt & 1) * 2]);
        }
        __syncthreads();
    }

    // epilogue
#pragma unroll
    for (int mt = 0; mt < 2; mt++) {
#pragma unroll
        for (int nt = 0; nt < 4; nt++) {
            const float* c = acc[mt][nt];
            const int col = n0 + nw * 32 + nt * 8 + (lane & 3) * 2;
            const float bx = bias[col], by = bias[col + 1];
            const int rbase = m0 + mw * 32 + mt * 16 + (lane >> 2);
#pragma unroll
            for (int half = 0; half < 2; half++) {
                int m = rbase + half * 8;
                float vx = c[half * 2 + 0] + bx;
                float vy = c[half * 2 + 1] + by;
                if (EPI == 1) { vx = gelu_exact(vx); vy = gelu_exact(vy); }
                if (EPI == 2) {
                    int dst = win_to_tok(m);
                    size_t idx = (size_t)dst * CDIM + col;
                    float2 res = *(const float2*)&R[idx];
                    *(float2*)((float*)C + idx) = make_float2(vx + res.x, vy + res.y);
                } else if (EPI == 3) {
                    size_t idx = (size_t)m * N + col;
                    float2 res = *(const float2*)&R[idx];
                    *(float2*)((float*)C + idx) = make_float2(vx + res.x, vy + res.y);
                } else {
                    __nv_bfloat162 o = __floats2bfloat162_rn(vx, vy);
                    *(__nv_bfloat162*)((__nv_bfloat16*)C + (size_t)m * N + col) = o;
                }
            }
        }
    }
}

// ---- Windowed attention (bf16 in/out, fp32 compute) ----
__global__ void attn_kernel(const __nv_bfloat16* __restrict__ qkv,
                            const float* __restrict__ rpb,
                            __nv_bfloat16* __restrict__ out) {
    const int bw = blockIdx.x;
    const int w = bw / NHEADS;
    const int h = bw - w * NHEADS;
    const int wi = (w >> 4) & 15;
    const int wj = w & 15;

    __shared__ float qs[64 * 33];
    __shared__ float ks[64 * 33];
    __shared__ float vs[64 * 33];
    __shared__ float ps[64 * 65];
    __shared__ float bshr[225];

    const int tid = threadIdx.x;
    const float scale = 0.1767766952966368811f;

    const __nv_bfloat16* base = qkv + (size_t)w * 64 * (3 * CDIM) + h * HD;
#pragma unroll
    for (int i = 0; i < 4; i++) {
        int idx = tid + 256 * i;          // 0..1023 pair slots
        int n = idx >> 4, p = (idx & 15) * 2;
        size_t r = (size_t)n * (3 * CDIM) + p;
        float2 q2 = __bfloat1622float2(*(const __nv_bfloat162*)(base + r));
        float2 k2 = __bfloat1622float2(*(const __nv_bfloat162*)(base + r + CDIM));
        float2 v2 = __bfloat1622float2(*(const __nv_bfloat162*)(base + r + 2 * CDIM));
        qs[n * 33 + p] = q2.x * scale; qs[n * 33 + p + 1] = q2.y * scale;
        ks[n * 33 + p] = k2.x;         ks[n * 33 + p + 1] = k2.y;
        vs[n * 33 + p] = v2.x;         vs[n * 33 + p + 1] = v2.y;
    }
    if (tid < 225) bshr[tid] = rpb[tid * NHEADS + h];
    __syncthreads();

    const int n = tid >> 2;
    const int mq = tid & 3;
    const int rn = n >> 3, cn = n & 7;
    const int lab_n = ((wi == 15) ? (rn < 4 ? 1 : 2) : 0) * 3 +
                      ((wj == 15) ? (cn < 4 ? 1 : 2) : 0);

    float qr[32];
#pragma unroll
    for (int d = 0; d < 32; d++) qr[d] = qs[n * 33 + d];

    float s[16];
#pragma unroll
    for (int mi = 0; mi < 16; mi++) {
        int m = mq * 16 + mi;
        float acc = 0.f;
#pragma unroll
        for (int d = 0; d < 32; d++) acc += qr[d] * ks[m * 33 + d];
        int rm = m >> 3, cm = m & 7;
        acc += bshr[(rn - rm + 7) * 15 + (cn - cm + 7)];
        int lab_m = ((wi == 15) ? (rm < 4 ? 1 : 2) : 0) * 3 +
                    ((wj == 15) ? (cm < 4 ? 1 : 2) : 0);
        if (lab_m != lab_n) acc -= 100.f;
        s[mi] = acc;
    }

    float mx = -1e30f;
#pragma unroll
    for (int mi = 0; mi < 16; mi++) mx = fmaxf(mx, s[mi]);
    mx = fmaxf(mx, __shfl_xor_sync(0xffffffffu, mx, 1));
    mx = fmaxf(mx, __shfl_xor_sync(0xffffffffu, mx, 2));
    float sum = 0.f;
#pragma unroll
    for (int mi = 0; mi < 16; mi++) { s[mi] = __expf(s[mi] - mx); sum += s[mi]; }
    sum += __shfl_xor_sync(0xffffffffu, sum, 1);
    sum += __shfl_xor_sync(0xffffffffu, sum, 2);
    float inv = 1.f / sum;
#pragma unroll
    for (int mi = 0; mi < 16; mi++) ps[n * 65 + mq * 16 + mi] = s[mi] * inv;
    __syncthreads();

    const int d0 = (tid & 3) * 8;
    float o[8];
#pragma unroll
    for (int dd = 0; dd < 8; dd++) o[dd] = 0.f;
    for (int m = 0; m < 64; m++) {
        float p = ps[n * 65 + m];
#pragma unroll
        for (int dd = 0; dd < 8; dd++) o[dd] += p * vs[m * 33 + d0 + dd];
    }
    __nv_bfloat16* orow = out + ((size_t)w * 64 + n) * CDIM + h * HD + d0;
    unsigned pk[4];
#pragma unroll
    for (int dd = 0; dd < 4; dd++) {
        __nv_bfloat162 t = __floats2bfloat162_rn(o[2 * dd], o[2 * dd + 1]);
        pk[dd] = *reinterpret_cast<unsigned*>(&t);
    }
    *(uint4*)orow = make_uint4(pk[0], pk[1], pk[2], pk[3]);
}

// -------------------- launch --------------------
extern "C" void kernel_launch(void* const* d_in, const int* in_sizes, int n_in,
                              void* d_out, int out_size) {
    (void)in_sizes; (void)n_in; (void)out_size;
    const float* x      = (const float*)d_in[0];
    const float* qkv_w  = (const float*)d_in[3];
    const float* qkv_b  = (const float*)d_in[4];
    const float* proj_w = (const float*)d_in[5];
    const float* proj_b = (const float*)d_in[6];
    const float* rpb    = (const float*)d_in[7];
    const float* n1w    = (const float*)d_in[8];
    const float* n1b    = (const float*)d_in[9];
    const float* n2w    = (const float*)d_in[10];
    const float* n2b    = (const float*)d_in[11];
    const float* w1     = (const float*)d_in[12];
    const float* b1     = (const float*)d_in[13];
    const float* w2     = (const float*)d_in[14];
    const float* b2     = (const float*)d_in[15];
    float* out = (float*)d_out;

    __nv_bfloat16 *winln, *qkvb, *attno, *h2, *mlpg;
    __nv_bfloat16 *qkvw_t, *projw_t, *w1_t, *w2_t;
    float* x2;
    cudaGetSymbolAddress((void**)&winln,  g_winln);
    cudaGetSymbolAddress((void**)&qkvb,   g_qkvb);
    cudaGetSymbolAddress((void**)&attno,  g_attno);
    cudaGetSymbolAddress((void**)&x2,     g_x2);
    cudaGetSymbolAddress((void**)&h2,     g_h2);
    cudaGetSymbolAddress((void**)&mlpg,   g_mlp);
    cudaGetSymbolAddress((void**)&qkvw_t, g_qkvw_t);
    cudaGetSymbolAddress((void**)&projw_t,g_projw_t);
    cudaGetSymbolAddress((void**)&w1_t,   g_w1_t);
    cudaGetSymbolAddress((void**)&w2_t,   g_w2_t);

    // 0. convert + transpose weights to bf16 [N][K]
    wconv_kernel<<<(192 * 576 + 255) / 256, 256>>>(qkv_w, qkvw_t, 192, 576);
    wconv_kernel<<<(192 * 192 + 255) / 256, 256>>>(proj_w, projw_t, 192, 192);
    wconv_kernel<<<(192 * 768 + 255) / 256, 256>>>(w1, w1_t, 192, 768);
    wconv_kernel<<<(768 * 192 + 255) / 256, 256>>>(w2, w2_t, 768, 192);

    // 1. LN1 + shift + window gather (fp32 -> bf16)
    ln_kernel<true><<<TOKENS / 8, 256>>>(x, winln, n1w, n1b);
    // 2. QKV GEMM [131072,192]x[192,576] -> bf16
    gemm_bf16<0, __nv_bfloat16><<<dim3(9, TOKENS / 128), 256>>>(
        winln, qkvw_t, qkv_b, qkvb, nullptr, TOKENS, 3 * CDIM, CDIM);
    // 3. attention
    attn_kernel<<<NWIN * NHEADS, 256>>>(qkvb, rpb, attno);
    // 4. proj GEMM + scatter + residual -> fp32 x2
    gemm_bf16<2, float><<<dim3(3, TOKENS / 128), 256>>>(
        attno, projw_t, proj_b, x2, x, TOKENS, CDIM, CDIM);
    // 5. LN2 (fp32 -> bf16)
    ln_kernel<false><<<TOKENS / 8, 256>>>(x2, h2, n2w, n2b);
    // 6. MLP1 + GELU -> bf16
    gemm_bf16<1, __nv_bfloat16><<<dim3(12, TOKENS / 128), 256>>>(
        h2, w1_t, b1, mlpg, nullptr, TOKENS, HIDDEN, CDIM);
    // 7. MLP2 + residual -> fp32 out
    gemm_bf16<3, float><<<dim3(3, TOKENS / 128), 256>>>(
        mlpg, w2_t, b2, out, x2, TOKENS, CDIM, HIDDEN);
}

// round 4
// speedup vs baseline: 5.2126x; 2.1819x over previous
#include <cuda_runtime.h>
#include <cuda_bf16.h>
#include <math.h>

#define TOKENS   131072
#define CDIM     192
#define NHEADS   6
#define HD       32
#define NWIN     2048
#define HIDDEN   768

// ---- scratch ----
__device__ __align__(16) __nv_bfloat16 g_winln[TOKENS * CDIM];
__device__ __align__(16) __nv_bfloat16 g_qkvb [TOKENS * 3 * CDIM];
__device__ __align__(16) __nv_bfloat16 g_attno[TOKENS * CDIM];
__device__ __align__(16) float         g_x2   [TOKENS * CDIM];
__device__ __align__(16) __nv_bfloat16 g_h2   [TOKENS * CDIM];
__device__ __align__(16) __nv_bfloat16 g_mlp  [TOKENS * HIDDEN];
__device__ __align__(16) __nv_bfloat16 g_qkvw_t[3 * CDIM * CDIM];
__device__ __align__(16) __nv_bfloat16 g_projw_t[CDIM * CDIM];
__device__ __align__(16) __nv_bfloat16 g_w1_t[HIDDEN * CDIM];
__device__ __align__(16) __nv_bfloat16 g_w2_t[CDIM * HIDDEN];

__device__ __forceinline__ int win_to_tok(int t) {
    int w = t >> 6, n = t & 63;
    int b  = w >> 8;
    int wi = (w >> 4) & 15;
    int wj = w & 15;
    int r = n >> 3, c = n & 7;
    int row = (wi * 8 + r + 4) & 127;
    int col = (wj * 8 + c + 4) & 127;
    return (b << 14) + (row << 7) + col;
}

// ---- helpers ----
__device__ __forceinline__ unsigned scvta(const void* p) {
    return (unsigned)__cvta_generic_to_shared(p);
}
__device__ __forceinline__ void cp16(void* dst, const void* src) {
    asm volatile("cp.async.cg.shared.global [%0], [%1], 16;" :: "r"(scvta(dst)), "l"(src));
}
__device__ __forceinline__ void cp_commit() { asm volatile("cp.async.commit_group;"); }
template <int N>
__device__ __forceinline__ void cp_wait() { asm volatile("cp.async.wait_group %0;" :: "n"(N)); }

__device__ __forceinline__ void ldsm4(unsigned* r, unsigned addr) {
    asm volatile("ldmatrix.sync.aligned.m8n8.x4.shared.b16 {%0,%1,%2,%3}, [%4];"
                 : "=r"(r[0]), "=r"(r[1]), "=r"(r[2]), "=r"(r[3]) : "r"(addr));
}
__device__ __forceinline__ void ldsm4t(unsigned* r, unsigned addr) {
    asm volatile("ldmatrix.sync.aligned.m8n8.x4.trans.shared.b16 {%0,%1,%2,%3}, [%4];"
                 : "=r"(r[0]), "=r"(r[1]), "=r"(r[2]), "=r"(r[3]) : "r"(addr));
}
__device__ __forceinline__ void mma_bf16(float* c, const unsigned* a, const unsigned* b) {
    asm volatile("mma.sync.aligned.m16n8k16.row.col.f32.bf16.bf16.f32 "
                 "{%0,%1,%2,%3},{%4,%5,%6,%7},{%8,%9},{%0,%1,%2,%3};"
                 : "+f"(c[0]), "+f"(c[1]), "+f"(c[2]), "+f"(c[3])
                 : "r"(a[0]), "r"(a[1]), "r"(a[2]), "r"(a[3]), "r"(b[0]), "r"(b[1]));
}
__device__ __forceinline__ int swz(int row, int chunk) {
    return row * 64 + ((chunk ^ ((row >> 1) & 3)) << 4);
}
__device__ __forceinline__ unsigned packbf(float x, float y) {
    __nv_bfloat162 t = __floats2bfloat162_rn(x, y);
    return *reinterpret_cast<unsigned*>(&t);
}
__device__ __forceinline__ float gelu_exact(float x) {
    return 0.5f * x * (1.0f + erff(x * 0.70710678118654752440f));
}

// ---- fused weight convert+transpose (all 4 weights, one launch) ----
#define WC1 110592            // qkv 192*576
#define WC2 (WC1 + 36864)     // proj 192*192
#define WC3 (WC2 + 147456)    // w1 192*768
#define WC4 (WC3 + 147456)    // w2 768*192
__global__ void wconv_all(const float* __restrict__ qkv_w, const float* __restrict__ proj_w,
                          const float* __restrict__ w1, const float* __restrict__ w2) {
    int idx = blockIdx.x * 256 + threadIdx.x;
    if (idx < WC1) {
        int k = idx / 576, n = idx - k * 576;
        g_qkvw_t[n * 192 + k] = __float2bfloat16_rn(qkv_w[idx]);
    } else if (idx < WC2) {
        int i = idx - WC1; int k = i / 192, n = i - k * 192;
        g_projw_t[n * 192 + k] = __float2bfloat16_rn(proj_w[i]);
    } else if (idx < WC3) {
        int i = idx - WC2; int k = i / 768, n = i - k * 768;
        g_w1_t[n * 192 + k] = __float2bfloat16_rn(w1[i]);
    } else if (idx < WC4) {
        int i = idx - WC3; int k = i / 192, n = i - k * 192;
        g_w2_t[n * 768 + k] = __float2bfloat16_rn(w2[i]);
    }
}

// ---- LayerNorm fp32 -> bf16 ----
template <bool GATHER>
__global__ void ln_kernel(const float* __restrict__ in, __nv_bfloat16* __restrict__ out,
                          const float* __restrict__ gamma, const float* __restrict__ beta) {
    int warp = (blockIdx.x * blockDim.x + threadIdx.x) >> 5;
    int lane = threadIdx.x & 31;
    if (warp >= TOKENS) return;
    int src = GATHER ? win_to_tok(warp) : warp;
    const float* row = in + (size_t)src * CDIM;

    float v[6];
    float mu = 0.f;
#pragma unroll
    for (int i = 0; i < 6; i++) { v[i] = row[lane + 32 * i]; mu += v[i]; }
#pragma unroll
    for (int o = 16; o; o >>= 1) mu += __shfl_xor_sync(0xffffffffu, mu, o);
    mu *= (1.f / 192.f);
    float var = 0.f;
#pragma unroll
    for (int i = 0; i < 6; i++) { float d = v[i] - mu; var += d * d; }
#pragma unroll
    for (int o = 16; o; o >>= 1) var += __shfl_xor_sync(0xffffffffu, var, o);
    var *= (1.f / 192.f);
    float rstd = rsqrtf(var + 1e-5f);

    __nv_bfloat16* orow = out + (size_t)warp * CDIM;
#pragma unroll
    for (int i = 0; i < 6; i++) {
        int c = lane + 32 * i;
        orow[c] = __float2bfloat16_rn((v[i] - mu) * rstd * gamma[c] + beta[c]);
    }
}

// ---- bf16 GEMM, cp.async 2-stage, fully unrolled K ----
// Block tile 128x64x32, 8 warps (4M x 2N). K = NSTEPS*32 compile-time.
#define BUFSZ ((128 + 64) * 64)
template <int EPI, int NSTEPS, typename OutT>
__global__ void __launch_bounds__(256) gemm_bf16(
        const __nv_bfloat16* __restrict__ A, const __nv_bfloat16* __restrict__ Bt,
        const float* __restrict__ bias, OutT* __restrict__ C,
        const float* __restrict__ R, int N) {
    __shared__ __align__(16) unsigned char smem[2 * BUFSZ];
    const int K = NSTEPS * 32;

    const int m0 = blockIdx.y * 128;
    const int n0 = blockIdx.x * 64;
    const int tid = threadIdx.x;
    const int lane = tid & 31;
    const int wid = tid >> 5;
    const int mw = wid & 3;
    const int nw = wid >> 2;

    const int a_row = tid >> 1;
    const int a_c0 = (tid & 1) * 2;
    const int b_row = tid >> 2;
    const int b_c = tid & 3;
    const __nv_bfloat16* aptr = A + (size_t)(m0 + a_row) * K + a_c0 * 8;
    const __nv_bfloat16* bptr = Bt + (size_t)(n0 + b_row) * K + b_c * 8;
    const int sA0 = swz(a_row, a_c0), sA1 = swz(a_row, a_c0 + 1), sB = swz(b_row, b_c);

    float acc[2][4][4];
#pragma unroll
    for (int i = 0; i < 2; i++)
#pragma unroll
        for (int j = 0; j < 4; j++)
#pragma unroll
            for (int l = 0; l < 4; l++) acc[i][j][l] = 0.f;

    const int rowOffA = (lane & 7) + ((lane >> 3) & 1) * 8;
    const int cHalfA = lane >> 4;
    const int rowA0 = mw * 32 + rowOffA;
    const int rowOffB = ((lane >> 4) << 3) + (lane & 7);
    const int cHalfB = (lane >> 3) & 1;
    const int rowB0 = nw * 32 + rowOffB;

    // stage 0
    {
        unsigned char* As = smem;
        unsigned char* Bs = smem + 128 * 64;
        cp16(As + sA0, aptr);
        cp16(As + sA1, aptr + 8);
        cp16(Bs + sB, bptr);
        cp_commit();
    }

#pragma unroll
    for (int step = 0; step < NSTEPS; step++) {
        if (step + 1 < NSTEPS) {
            unsigned char* As = smem + ((step + 1) & 1) * BUFSZ;
            unsigned char* Bs = As + 128 * 64;
            cp16(As + sA0, aptr + (step + 1) * 32);
            cp16(As + sA1, aptr + (step + 1) * 32 + 8);
            cp16(Bs + sB, bptr + (step + 1) * 32);
            cp_commit();
            cp_wait<1>();
        } else {
            cp_wait<0>();
        }
        __syncthreads();

        const unsigned As_u = scvta(smem + (step & 1) * BUFSZ);
        const unsigned Bs_u = As_u + 128 * 64;
#pragma unroll
        for (int s = 0; s < 2; s++) {
            unsigned af[2][4], bf[2][4];
            const int chA = 2 * s + cHalfA;
            const int chB = 2 * s + cHalfB;
#pragma unroll
            for (int t = 0; t < 2; t++) {
                int row = rowA0 + t * 16;
                ldsm4(af[t], As_u + row * 64 + ((chA ^ ((row >> 1) & 3)) << 4));
            }
#pragma unroll
            for (int t = 0; t < 2; t++) {
                int row = rowB0 + t * 16;
                ldsm4(bf[t], Bs_u + row * 64 + ((chB ^ ((row >> 1) & 3)) << 4));
            }
#pragma unroll
            for (int mt = 0; mt < 2; mt++)
#pragma unroll
                for (int nt = 0; nt < 4; nt++)
                    mma_bf16(acc[mt][nt], af[mt], &bf[nt >> 1][(nt & 1) * 2]);
        }
        __syncthreads();
    }

#pragma unroll
    for (int mt = 0; mt < 2; mt++) {
#pragma unroll
        for (int nt = 0; nt < 4; nt++) {
            const float* c = acc[mt][nt];
            const int col = n0 + nw * 32 + nt * 8 + (lane & 3) * 2;
            const float bx = bias[col], by = bias[col + 1];
            const int rbase = m0 + mw * 32 + mt * 16 + (lane >> 2);
#pragma unroll
            for (int half = 0; half < 2; half++) {
                int m = rbase + half * 8;
                float vx = c[half * 2 + 0] + bx;
                float vy = c[half * 2 + 1] + by;
                if (EPI == 1) { vx = gelu_exact(vx); vy = gelu_exact(vy); }
                if (EPI == 2) {
                    int dst = win_to_tok(m);
                    size_t idx = (size_t)dst * CDIM + col;
                    float2 res = *(const float2*)&R[idx];
                    *(float2*)((float*)C + idx) = make_float2(vx + res.x, vy + res.y);
                } else if (EPI == 3) {
                    size_t idx = (size_t)m * N + col;
                    float2 res = *(const float2*)&R[idx];
                    *(float2*)((float*)C + idx) = make_float2(vx + res.x, vy + res.y);
                } else {
                    __nv_bfloat162 o = __floats2bfloat162_rn(vx, vy);
                    *(__nv_bfloat162*)((__nv_bfloat16*)C + (size_t)m * N + col) = o;
                }
            }
        }
    }
}

// ---- tensor-core windowed attention: one block per window, 128 threads, loop heads ----
__global__ void __launch_bounds__(128) attn_mma(const __nv_bfloat16* __restrict__ qkv,
                                                const float* __restrict__ rpb,
                                                __nv_bfloat16* __restrict__ out) {
    const int w = blockIdx.x;
    const int wi = (w >> 4) & 15;
    const int wj = w & 15;

    __shared__ __align__(16) unsigned char qs[64 * 64];
    __shared__ __align__(16) unsigned char ks[64 * 64];
    __shared__ __align__(16) unsigned char vs[64 * 64];
    __shared__ float bshr[225];

    const int tid = threadIdx.x;
    const int lane = tid & 31;
    const int wid = tid >> 5;
    const float scale = 0.1767766952966368811f;

    const unsigned qs_u = scvta(qs), ks_u = scvta(ks), vs_u = scvta(vs);

    // per-thread smem-fill assignment: 2 chunks per tensor
    const int f_row = tid >> 1;
    const int f_c0 = (tid & 1) * 2;
    const size_t f_src = (size_t)(w * 64 + f_row) * (3 * CDIM) + f_c0 * 8;
    const int fs0 = swz(f_row, f_c0), fs1 = swz(f_row, f_c0 + 1);

    // fragment row assignments
    const int rowOffA = (lane & 7) + ((lane >> 3) & 1) * 8;
    const int cHalfA = lane >> 4;
    const int rowA0 = wid * 16 + rowOffA;
    const int rowOffB = ((lane >> 4) << 3) + (lane & 7);
    const int cHalfB = (lane >> 3) & 1;

    // query-row labels & coords (rows r0 = wid*16 + lane>>2, r1 = r0+8)
    const int r0 = wid * 16 + (lane >> 2);
    const int r1 = r0 + 8;
    const int rn0 = r0 >> 3, cn0 = r0 & 7;
    const int rn1 = r1 >> 3, cn1 = r1 & 7;
    const int li = (wi == 15), lj = (wj == 15);
    const int lab0 = (li ? (rn0 < 4 ? 1 : 2) : 0) * 3 + (lj ? (cn0 < 4 ? 1 : 2) : 0);
    const int lab1 = (li ? (rn1 < 4 ? 1 : 2) : 0) * 3 + (lj ? (cn1 < 4 ? 1 : 2) : 0);

    for (int h = 0; h < NHEADS; h++) {
        __syncthreads();   // protect smem from previous head's readers
        {
            const __nv_bfloat16* src = qkv + f_src + h * HD;
            cp16(qs + fs0, src);            cp16(qs + fs1, src + 8);
            cp16(ks + fs0, src + CDIM);     cp16(ks + fs1, src + CDIM + 8);
            cp16(vs + fs0, src + 2 * CDIM); cp16(vs + fs1, src + 2 * CDIM + 8);
            cp_commit();
        }
        for (int i = tid; i < 225; i += 128) bshr[i] = rpb[i * NHEADS + h];
        cp_wait<0>();
        __syncthreads();

        // ---- S = Q K^T : warp owns rows [wid*16, wid*16+16), all 64 cols ----
        float sacc[8][4];
#pragma unroll
        for (int i = 0; i < 8; i++)
#pragma unroll
            for (int j = 0; j < 4; j++) sacc[i][j] = 0.f;

#pragma unroll
        for (int kk = 0; kk < 2; kk++) {
            unsigned aq[4];
            {
                int row = rowA0;
                int ch = kk * 2 + cHalfA;
                ldsm4(aq, qs_u + row * 64 + ((ch ^ ((row >> 1) & 3)) << 4));
            }
#pragma unroll
            for (int nt2 = 0; nt2 < 4; nt2++) {
                unsigned bk[4];
                int row = nt2 * 16 + rowOffB;
                int ch = kk * 2 + cHalfB;
                ldsm4(bk, ks_u + row * 64 + ((ch ^ ((row >> 1) & 3)) << 4));
                mma_bf16(sacc[nt2 * 2 + 0], aq, &bk[0]);
                mma_bf16(sacc[nt2 * 2 + 1], aq, &bk[2]);
            }
        }

        // ---- scale + bias + mask ----
#pragma unroll
        for (int nt = 0; nt < 8; nt++) {
#pragma unroll
            for (int j = 0; j < 4; j++) {
                int m = nt * 8 + (lane & 3) * 2 + (j & 1);
                int rm = m >> 3, cm = m & 7;
                int labm = (li ? (rm < 4 ? 1 : 2) : 0) * 3 + (lj ? (cm < 4 ? 1 : 2) : 0);
                float v = sacc[nt][j] * scale;
                if (j < 2) {
                    v += bshr[(rn0 - rm + 7) * 15 + (cn0 - cm + 7)];
                    if (labm != lab0) v -= 100.f;
                } else {
                    v += bshr[(rn1 - rm + 7) * 15 + (cn1 - cm + 7)];
                    if (labm != lab1) v -= 100.f;
                }
                sacc[nt][j] = v;
            }
        }

        // ---- softmax (deferred normalization) ----
        float mx0 = -1e30f, mx1 = -1e30f;
#pragma unroll
        for (int nt = 0; nt < 8; nt++) {
            mx0 = fmaxf(mx0, fmaxf(sacc[nt][0], sacc[nt][1]));
            mx1 = fmaxf(mx1, fmaxf(sacc[nt][2], sacc[nt][3]));
        }
        mx0 = fmaxf(mx0, __shfl_xor_sync(0xffffffffu, mx0, 1));
        mx0 = fmaxf(mx0, __shfl_xor_sync(0xffffffffu, mx0, 2));
        mx1 = fmaxf(mx1, __shfl_xor_sync(0xffffffffu, mx1, 1));
        mx1 = fmaxf(mx1, __shfl_xor_sync(0xffffffffu, mx1, 2));
        float sum0 = 0.f, sum1 = 0.f;
#pragma unroll
        for (int nt = 0; nt < 8; nt++) {
            sacc[nt][0] = __expf(sacc[nt][0] - mx0); sum0 += sacc[nt][0];
            sacc[nt][1] = __expf(sacc[nt][1] - mx0); sum0 += sacc[nt][1];
            sacc[nt][2] = __expf(sacc[nt][2] - mx1); sum1 += sacc[nt][2];
            sacc[nt][3] = __expf(sacc[nt][3] - mx1); sum1 += sacc[nt][3];
        }
        sum0 += __shfl_xor_sync(0xffffffffu, sum0, 1);
        sum0 += __shfl_xor_sync(0xffffffffu, sum0, 2);
        sum1 += __shfl_xor_sync(0xffffffffu, sum1, 1);
        sum1 += __shfl_xor_sync(0xffffffffu, sum1, 2);
        const float inv0 = 1.f / sum0, inv1 = 1.f / sum1;

        // ---- O = P V : K=64 (4 k16 steps), N=32 (4 n-tiles) ----
        float oacc[4][4];
#pragma unroll
        for (int i = 0; i < 4; i++)
#pragma unroll
            for (int j = 0; j < 4; j++) oacc[i][j] = 0.f;

#pragma unroll
        for (int kk2 = 0; kk2 < 4; kk2++) {
            unsigned ap[4];
            ap[0] = packbf(sacc[2 * kk2][0], sacc[2 * kk2][1]);
            ap[1] = packbf(sacc[2 * kk2][2], sacc[2 * kk2][3]);
            ap[2] = packbf(sacc[2 * kk2 + 1][0], sacc[2 * kk2 + 1][1]);
            ap[3] = packbf(sacc[2 * kk2 + 1][2], sacc[2 * kk2 + 1][3]);
#pragma unroll
            for (int nt2 = 0; nt2 < 2; nt2++) {
                unsigned bv[4];
                int row = kk2 * 16 + (lane & 7) + ((lane >> 3) & 1) * 8;
                int ch = 2 * nt2 + (lane >> 4);
                ldsm4t(bv, vs_u + row * 64 + ((ch ^ ((row >> 1) & 3)) << 4));
                mma_bf16(oacc[nt2 * 2 + 0], ap, &bv[0]);
                mma_bf16(oacc[nt2 * 2 + 1], ap, &bv[2]);
            }
        }

        // ---- write O (normalized) ----
        const int colb = h * HD + (lane & 3) * 2;
        __nv_bfloat16* o0 = out + ((size_t)(w * 64 + r0)) * CDIM + colb;
        __nv_bfloat16* o1 = out + ((size_t)(w * 64 + r1)) * CDIM + colb;
#pragma unroll
        for (int nt = 0; nt < 4; nt++) {
            unsigned p0 = packbf(oacc[nt][0] * inv0, oacc[nt][1] * inv0);
            unsigned p1 = packbf(oacc[nt][2] * inv1, oacc[nt][3] * inv1);
            *(unsigned*)(o0 + nt * 8) = p0;
            *(unsigned*)(o1 + nt * 8) = p1;
        }
    }
}

// -------------------- launch --------------------
extern "C" void kernel_launch(void* const* d_in, const int* in_sizes, int n_in,
                              void* d_out, int out_size) {
    (void)in_sizes; (void)n_in; (void)out_size;
    const float* x      = (const float*)d_in[0];
    const float* qkv_w  = (const float*)d_in[3];
    const float* qkv_b  = (const float*)d_in[4];
    const float* proj_w = (const float*)d_in[5];
    const float* proj_b = (const float*)d_in[6];
    const float* rpb    = (const float*)d_in[7];
    const float* n1w    = (const float*)d_in[8];
    const float* n1b    = (const float*)d_in[9];
    const float* n2w    = (const float*)d_in[10];
    const float* n2b    = (const float*)d_in[11];
    const float* w1     = (const float*)d_in[12];
    const float* b1     = (const float*)d_in[13];
    const float* w2     = (const float*)d_in[14];
    const float* b2     = (const float*)d_in[15];
    float* out = (float*)d_out;

    __nv_bfloat16 *winln, *qkvb, *attno, *h2, *mlpg;
    __nv_bfloat16 *qkvw_t, *projw_t, *w1_t, *w2_t;
    float* x2;
    cudaGetSymbolAddress((void**)&winln,  g_winln);
    cudaGetSymbolAddress((void**)&qkvb,   g_qkvb);
    cudaGetSymbolAddress((void**)&attno,  g_attno);
    cudaGetSymbolAddress((void**)&x2,     g_x2);
    cudaGetSymbolAddress((void**)&h2,     g_h2);
    cudaGetSymbolAddress((void**)&mlpg,   g_mlp);
    cudaGetSymbolAddress((void**)&qkvw_t, g_qkvw_t);
    cudaGetSymbolAddress((void**)&projw_t,g_projw_t);
    cudaGetSymbolAddress((void**)&w1_t,   g_w1_t);
    cudaGetSymbolAddress((void**)&w2_t,   g_w2_t);

    wconv_all<<<(WC4 + 255) / 256, 256>>>(qkv_w, proj_w, w1, w2);

    ln_kernel<true><<<TOKENS / 8, 256>>>(x, winln, n1w, n1b);
    gemm_bf16<0, 6, __nv_bfloat16><<<dim3(9, TOKENS / 128), 256>>>(
        winln, qkvw_t, qkv_b, qkvb, nullptr, 3 * CDIM);
    attn_mma<<<NWIN, 128>>>(qkvb, rpb, attno);
    gemm_bf16<2, 6, float><<<dim3(3, TOKENS / 128), 256>>>(
        attno, projw_t, proj_b, x2, x, CDIM);
    ln_kernel<false><<<TOKENS / 8, 256>>>(x2, h2, n2w, n2b);
    gemm_bf16<1, 6, __nv_bfloat16><<<dim3(12, TOKENS / 128), 256>>>(
        h2, w1_t, b1, mlpg, nullptr, HIDDEN);
    gemm_bf16<3, 24, float><<<dim3(3, TOKENS / 128), 256>>>(
        mlpg, w2_t, b2, out, x2, CDIM);
}